// round 15
// baseline (speedup 1.0000x reference)
#include <cuda_runtime.h>
#include <cuda_fp16.h>
#include <math.h>
#include <stdint.h>

#define NN 8
#define CC 1024
#define BB 2048

// ---- scratch (device globals; no allocation allowed) ----
__device__ __half g_Kh[(size_t)NN * CC * BB];   // K [o][b] fp16
__device__ __half g_Qh[(size_t)NN * CC * BB];   // Q [o][b] fp16
__device__ __half g_E [(size_t)NN * BB * BB];   // E = exp(Y) [b][k'] fp16
__device__ __half g_Xh[(size_t)NN * CC * BB];   // X fp16 [c][b]
__device__ __half g_Wkh[CC * CC];
__device__ __half g_Wqh[CC * CC];
__device__ float  g_stats[3 * NN * BB];         // [DK2 | DQ2 | S], zeroed each launch

// ---------------------------------------------------------------------------
__device__ __forceinline__ void cp16s(uint32_t s, const __half* g) {
    asm volatile("cp.async.cg.shared.global [%0], [%1], 16;" :: "r"(s), "l"(g));
}
#define CP_COMMIT() asm volatile("cp.async.commit_group;")

__device__ __forceinline__ void ldm4(uint32_t (&r)[4], uint32_t a) {
    asm volatile("ldmatrix.sync.aligned.m8n8.x4.shared.b16 {%0,%1,%2,%3}, [%4];"
                 : "=r"(r[0]), "=r"(r[1]), "=r"(r[2]), "=r"(r[3]) : "r"(a));
}
__device__ __forceinline__ void ldm4t(uint32_t (&r)[4], uint32_t a) {
    asm volatile("ldmatrix.sync.aligned.m8n8.x4.trans.shared.b16 {%0,%1,%2,%3}, [%4];"
                 : "=r"(r[0]), "=r"(r[1]), "=r"(r[2]), "=r"(r[3]) : "r"(a));
}
__device__ __forceinline__ void mma16(float (&d)[4], const uint32_t (&a)[4],
                                      const uint32_t (&b)[2]) {
    asm volatile(
        "mma.sync.aligned.m16n8k16.row.col.f32.f16.f16.f32 "
        "{%0,%1,%2,%3}, {%4,%5,%6,%7}, {%8,%9}, {%0,%1,%2,%3};"
        : "+f"(d[0]), "+f"(d[1]), "+f"(d[2]), "+f"(d[3])
        : "r"(a[0]), "r"(a[1]), "r"(a[2]), "r"(a[3]), "r"(b[0]), "r"(b[1]));
}

// exp(x) for |x| <= ~1.05 via Taylor to x^7 (rel err ~1.4e-5) — pure FMA.
__device__ __forceinline__ float exp_poly(float x)
{
    float r = fmaf(x, 1.f / 7.f, 1.f);
    r = fmaf(r * x, 1.f / 6.f, 1.f);
    r = fmaf(r * x, 1.f / 5.f, 1.f);
    r = fmaf(r * x, 1.f / 4.f, 1.f);
    r = fmaf(r * x, 1.f / 3.f, 1.f);
    r = fmaf(r * x, 0.5f, 1.f);
    return fmaf(r, x, 1.f);
}

// ===========================================================================
// FP16 warp-MMA GEMM: CTA 128x128, 4 warps (2m x 2n), warp tile 64x64,
// BK=64, 2-stage cp.async, ldmatrix frag loads, 3 CTAs/SM.
// n0: batch base offset (nb = n0 + blockIdx.z) — enables per-batch splits.
// MODE 0: proj  — out half: acc + bias[m]; fused column sum-of-squares -> aux0
// MODE 1: score — y = acc * irq[m] * irk[n] (factorized rsqrt);
//                 out half exp(y); fused column sums of exp -> aux0
// MODE 2: mix   — out float: acc * (1 / aux0[n])
// ===========================================================================
#define BK 64
#define ARM_STR 72     // A row-major smem stride (halves): 64 + 8 pad
#define KM_STR 136     // k-major / B smem stride (halves): 128 + 8 pad

template <int MODE, int KDIM, bool AKM, typename OutT>
__global__ __launch_bounds__(128, 3)
void gemm_h(const __half* __restrict__ A, int lda, size_t strA,
            const __half* __restrict__ B, int ldb, size_t strB,
            OutT* __restrict__ C, int ldc, size_t strC,
            const float* __restrict__ bias,
            float* __restrict__ aux0,
            const float* __restrict__ dq2_all,
            const float* __restrict__ dk2_all,
            int n0)
{
    constexpr int SA = AKM ? BK * KM_STR : 128 * ARM_STR;   // halves per stage
    constexpr int SB = BK * KM_STR;
    extern __shared__ __half dsm[];
    __shared__ float s_aux[128];    // MODE1: rsqrt(dk2) ; MODE2: 1/S
    __shared__ float s_red[128];    // column partial reduce

    const int nb = n0 + blockIdx.z;
    const __half* An = A + (size_t)nb * strA;
    const __half* Bn = B + (size_t)nb * strB;
    OutT* Cn = C + (size_t)nb * strC;
    const int row0 = blockIdx.y * 128;
    const int col0 = blockIdx.x * 128;

    const int tid = threadIdx.x;
    const int lane = tid & 31;
    const int wid = tid >> 5;
    const int wm = wid >> 1;
    const int wn = wid & 1;
    const int l7 = lane & 7;
    const int g = lane >> 3;

    s_red[tid] = 0.f;
    if (MODE == 1)
        s_aux[tid] = rsqrtf(fmaxf(dk2_all[(size_t)nb * BB + col0 + tid], 1e-6f));
    if (MODE == 2)
        s_aux[tid] = 1.f / aux0[(size_t)nb * BB + col0 + tid];

    float acc[4][8][4] = {};

    auto ldA = [&](int st, int kt) {
        uint32_t sb = (uint32_t)__cvta_generic_to_shared(dsm + st * SA);
        if (!AKM) {
            #pragma unroll
            for (int i = tid; i < 1024; i += 128) {      // 128 rows x 8 chunks
                int m = i >> 3, c = i & 7;
                cp16s(sb + (m * ARM_STR + c * 8) * 2,
                      An + (size_t)(row0 + m) * lda + kt * BK + c * 8);
            }
        } else {
            #pragma unroll
            for (int i = tid; i < 1024; i += 128) {      // 64 k-rows x 16 chunks
                int k = i >> 4, c = i & 15;
                cp16s(sb + (k * KM_STR + c * 8) * 2,
                      An + (size_t)(kt * BK + k) * lda + row0 + c * 8);
            }
        }
    };
    auto ldB = [&](int st, int kt) {
        uint32_t sb = (uint32_t)__cvta_generic_to_shared(dsm + 2 * SA + st * SB);
        #pragma unroll
        for (int i = tid; i < 1024; i += 128) {          // 64 k-rows x 16 chunks
            int k = i >> 4, c = i & 15;
            cp16s(sb + (k * KM_STR + c * 8) * 2,
                  Bn + (size_t)(kt * BK + k) * ldb + col0 + c * 8);
        }
    };

    constexpr int KT = KDIM / BK;

    ldA(0, 0); ldB(0, 0); CP_COMMIT();

    for (int kt = 0; kt < KT; kt++) {
        const int buf = kt & 1;
        if (kt + 1 < KT) {
            ldA(buf ^ 1, kt + 1);
            ldB(buf ^ 1, kt + 1);
            CP_COMMIT();
            asm volatile("cp.async.wait_group 1;");
        } else {
            asm volatile("cp.async.wait_group 0;");
        }
        __syncthreads();

        uint32_t aA = (uint32_t)__cvta_generic_to_shared(dsm + buf * SA);
        uint32_t aB = (uint32_t)__cvta_generic_to_shared(dsm + 2 * SA + buf * SB);

        #pragma unroll
        for (int ks = 0; ks < 4; ks++) {
            const int kb = ks * 16;
            uint32_t af[4][4];
            uint32_t bf[8][2];

            #pragma unroll
            for (int mi = 0; mi < 4; mi++) {
                if (!AKM) {
                    int m = wm * 64 + mi * 16 + l7 + (g & 1) * 8;
                    int k = kb + (g >> 1) * 8;
                    ldm4(af[mi], aA + (m * ARM_STR + k) * 2);
                } else {
                    int k = kb + (g >> 1) * 8 + l7;
                    int m = wm * 64 + mi * 16 + (g & 1) * 8;
                    ldm4t(af[mi], aA + (k * KM_STR + m) * 2);
                }
            }
            #pragma unroll
            for (int j = 0; j < 4; j++) {
                int k = kb + (g & 1) * 8 + l7;
                int nn = wn * 64 + j * 16 + (g >> 1) * 8;
                uint32_t r[4];
                ldm4t(r, aB + (k * KM_STR + nn) * 2);
                bf[2 * j][0] = r[0];      bf[2 * j][1] = r[1];
                bf[2 * j + 1][0] = r[2];  bf[2 * j + 1][1] = r[3];
            }
            #pragma unroll
            for (int mi = 0; mi < 4; mi++)
                #pragma unroll
                for (int ni = 0; ni < 8; ni++)
                    mma16(acc[mi][ni], af[mi], bf[ni]);
        }
        __syncthreads();
    }

    // ---- epilogue (ni outer, mi inner; per-column partials for fusion) ----
    const int lr = lane >> 2, lc = lane & 3;

    float rA[4], rB[4];   // per-mi rows: bias (MODE0) or rsqrt(dq2) (MODE1)
    #pragma unroll
    for (int mi = 0; mi < 4; mi++) {
        const int m = row0 + wm * 64 + mi * 16 + lr;
        if (MODE == 0) { rA[mi] = bias[m]; rB[mi] = bias[m + 8]; }
        if (MODE == 1) {
            rA[mi] = rsqrtf(fmaxf(dq2_all[(size_t)nb * BB + m], 1e-6f));
            rB[mi] = rsqrtf(fmaxf(dq2_all[(size_t)nb * BB + m + 8], 1e-6f));
        }
    }

    #pragma unroll
    for (int ni = 0; ni < 8; ni++) {
        const int cl = wn * 64 + ni * 8 + 2 * lc;
        const int nn = col0 + cl;
        float c0 = 0.f, c1 = 0.f;
        float x0 = 0.f, x1 = 0.f;   // MODE1: irk ; MODE2: 1/S
        if (MODE == 1 || MODE == 2) { x0 = s_aux[cl]; x1 = s_aux[cl + 1]; }

        #pragma unroll
        for (int mi = 0; mi < 4; mi++) {
            const int m = row0 + wm * 64 + mi * 16 + lr;
            float v0 = acc[mi][ni][0], v1 = acc[mi][ni][1];
            float v2 = acc[mi][ni][2], v3 = acc[mi][ni][3];
            if (MODE == 0) {
                v0 += rA[mi]; v1 += rA[mi]; v2 += rB[mi]; v3 += rB[mi];
                c0 += v0 * v0 + v2 * v2;
                c1 += v1 * v1 + v3 * v3;
            } else if (MODE == 1) {
                v0 = exp_poly(v0 * rA[mi] * x0);
                v1 = exp_poly(v1 * rA[mi] * x1);
                v2 = exp_poly(v2 * rB[mi] * x0);
                v3 = exp_poly(v3 * rB[mi] * x1);
                c0 += v0 + v2;
                c1 += v1 + v3;
            } else {
                v0 *= x0; v1 *= x1; v2 *= x0; v3 *= x1;
            }
            if (MODE == 2) {
                *reinterpret_cast<float2*>((float*)&Cn[(size_t)m * ldc + nn]) =
                    make_float2(v0, v1);
                *reinterpret_cast<float2*>((float*)&Cn[(size_t)(m + 8) * ldc + nn]) =
                    make_float2(v2, v3);
            } else {
                *reinterpret_cast<__half2*>((__half*)&Cn[(size_t)m * ldc + nn]) =
                    __floats2half2_rn(v0, v1);
                *reinterpret_cast<__half2*>((__half*)&Cn[(size_t)(m + 8) * ldc + nn]) =
                    __floats2half2_rn(v2, v3);
            }
        }
        if (MODE == 0 || MODE == 1) {
            atomicAdd(&s_red[cl], c0);
            atomicAdd(&s_red[cl + 1], c1);
        }
    }

    if (MODE == 0 || MODE == 1) {
        __syncthreads();
        atomicAdd(&aux0[(size_t)nb * BB + col0 + tid], s_red[tid]);
    }
}

// ---------------------------------------------------------------------------
__global__ __launch_bounds__(256)
void to_half_kernel(const float* __restrict__ in, __half* __restrict__ out, int n4)
{
    int i = blockIdx.x * 256 + threadIdx.x;
    int stride = gridDim.x * 256;
    for (; i < n4; i += stride) {
        float4 v = reinterpret_cast<const float4*>(in)[i];
        __half2* o = reinterpret_cast<__half2*>(out) + 2 * i;
        o[0] = __floats2half2_rn(v.x, v.y);
        o[1] = __floats2half2_rn(v.z, v.w);
    }
}

// ---------------------------------------------------------------------------
extern "C" void kernel_launch(void* const* d_in, const int* in_sizes, int n_in,
                              void* d_out, int out_size)
{
    const float* X    = (const float*)d_in[0];
    const float* Wk_w = (const float*)d_in[1];
    const float* Wk_b = (const float*)d_in[2];
    const float* Wq_w = (const float*)d_in[3];
    const float* Wq_b = (const float*)d_in[4];
    float* Z = (float*)d_out;

    __half* Kh;  cudaGetSymbolAddress((void**)&Kh,  g_Kh);
    __half* Qh;  cudaGetSymbolAddress((void**)&Qh,  g_Qh);
    __half* Ed;  cudaGetSymbolAddress((void**)&Ed,  g_E);
    __half* Xh;  cudaGetSymbolAddress((void**)&Xh,  g_Xh);
    __half* Wkh; cudaGetSymbolAddress((void**)&Wkh, g_Wkh);
    __half* Wqh; cudaGetSymbolAddress((void**)&Wqh, g_Wqh);
    float* stats; cudaGetSymbolAddress((void**)&stats, g_stats);
    float* DK2 = stats;
    float* DQ2 = stats + NN * BB;
    float* Sv  = stats + 2 * NN * BB;

    const size_t sXn = (size_t)CC * BB;
    const size_t sYn = (size_t)BB * BB;

    // dynamic smem (2 stages, BK=64)
    constexpr int smem_rm  = 2 * (128 * ARM_STR + BK * KM_STR) * 2;  // 71,680 B
    constexpr int smem_akm = 2 * (BK * KM_STR * 2) * 2;              // 69,632 B

    static cudaStream_t s1 = nullptr, s2 = nullptr;
    static cudaEvent_t eS, e0, ek, eq, ej;
    if (s1 == nullptr) {
        cudaStreamCreateWithFlags(&s1, cudaStreamNonBlocking);
        cudaStreamCreateWithFlags(&s2, cudaStreamNonBlocking);
        cudaEventCreateWithFlags(&eS, cudaEventDisableTiming);
        cudaEventCreateWithFlags(&e0, cudaEventDisableTiming);
        cudaEventCreateWithFlags(&ek, cudaEventDisableTiming);
        cudaEventCreateWithFlags(&eq, cudaEventDisableTiming);
        cudaEventCreateWithFlags(&ej, cudaEventDisableTiming);
        cudaFuncSetAttribute(gemm_h<0, CC, false, __half>,
                             cudaFuncAttributeMaxDynamicSharedMemorySize, smem_rm);
        cudaFuncSetAttribute(gemm_h<1, CC, true, __half>,
                             cudaFuncAttributeMaxDynamicSharedMemorySize, smem_akm);
        cudaFuncSetAttribute(gemm_h<2, BB, false, float>,
                             cudaFuncAttributeMaxDynamicSharedMemorySize, smem_rm);
    }

    // ---- fork point (default stream = capture stream) ----
    cudaEventRecord(eS, 0);

    // default: zero fused accumulators + convert X
    cudaMemsetAsync(stats, 0, 3 * NN * BB * sizeof(float));
    to_half_kernel<<<2048, 256>>>(X, Xh, (int)(NN * sXn / 4));
    cudaEventRecord(e0, 0);

    // s1: convert Wk, then proj K (dep: X converted)
    cudaStreamWaitEvent(s1, eS, 0);
    to_half_kernel<<<256, 256, 0, s1>>>(Wk_w, Wkh, CC * CC / 4);
    cudaStreamWaitEvent(s1, e0, 0);
    gemm_h<0, CC, false, __half><<<dim3(BB / 128, CC / 128, NN), 128, smem_rm, s1>>>(
        Wkh, CC, 0, Xh, BB, sXn, Kh, BB, sXn, Wk_b, DK2, nullptr, nullptr, 0);
    cudaEventRecord(ek, s1);

    // s2: convert Wq, then proj Q
    cudaStreamWaitEvent(s2, eS, 0);
    to_half_kernel<<<256, 256, 0, s2>>>(Wq_w, Wqh, CC * CC / 4);
    cudaStreamWaitEvent(s2, e0, 0);
    gemm_h<0, CC, false, __half><<<dim3(BB / 128, CC / 128, NN), 128, smem_rm, s2>>>(
        Wqh, CC, 0, Xh, BB, sXn, Qh, BB, sXn, Wq_b, DQ2, nullptr, nullptr, 0);
    cudaEventRecord(eq, s2);

    // ---- join: both streams must see both projections ----
    cudaStreamWaitEvent(s1, eq, 0);
    cudaStreamWaitEvent(s2, ek, 0);

    // ---- pipelined score -> mix, split by batch halves across streams ----
    // s1: batches 0..3
    gemm_h<1, CC, true, __half><<<dim3(BB / 128, BB / 128, NN / 2), 128, smem_akm, s1>>>(
        Qh, BB, sXn, Kh, BB, sXn, Ed, BB, sYn, nullptr, Sv, DQ2, DK2, 0);
    gemm_h<2, BB, false, float><<<dim3(BB / 128, CC / 128, NN / 2), 128, smem_rm, s1>>>(
        Xh, BB, sXn, Ed, BB, sYn, Z, BB, sXn, nullptr, Sv, nullptr, nullptr, 0);
    cudaEventRecord(ek, s1);

    // s2: batches 4..7
    gemm_h<1, CC, true, __half><<<dim3(BB / 128, BB / 128, NN / 2), 128, smem_akm, s2>>>(
        Qh, BB, sXn, Kh, BB, sXn, Ed, BB, sYn, nullptr, Sv, DQ2, DK2, NN / 2);
    gemm_h<2, BB, false, float><<<dim3(BB / 128, CC / 128, NN / 2), 128, smem_rm, s2>>>(
        Xh, BB, sXn, Ed, BB, sYn, Z, BB, sXn, nullptr, Sv, nullptr, nullptr, NN / 2);
    cudaEventRecord(eq, s2);

    // ---- final join back onto the capture (default) stream ----
    cudaStreamWaitEvent(0, ek, 0);
    cudaStreamWaitEvent(0, eq, 0);
}

// round 16
// speedup vs baseline: 1.0453x; 1.0453x over previous
#include <cuda_runtime.h>
#include <cuda_fp16.h>
#include <math.h>
#include <stdint.h>

#define NN 8
#define CC 1024
#define BB 2048

// ---- scratch (device globals; no allocation allowed) ----
__device__ __half g_Kh[(size_t)NN * CC * BB];   // K [o][b] fp16
__device__ __half g_Qh[(size_t)NN * CC * BB];   // Q [o][b] fp16
__device__ __half g_E [(size_t)NN * BB * BB];   // E = exp(Y) [b][k'] fp16
__device__ __half g_Xh[(size_t)NN * CC * BB];   // X fp16 [c][b]
__device__ __half g_Wkh[CC * CC];
__device__ __half g_Wqh[CC * CC];
__device__ float  g_stats[3 * NN * BB];         // [DK2 | DQ2 | S], zeroed each launch

// ---------------------------------------------------------------------------
__device__ __forceinline__ void cp16s(uint32_t s, const __half* g) {
    asm volatile("cp.async.cg.shared.global [%0], [%1], 16;" :: "r"(s), "l"(g));
}
#define CP_COMMIT() asm volatile("cp.async.commit_group;")

__device__ __forceinline__ void ldm4(uint32_t (&r)[4], uint32_t a) {
    asm volatile("ldmatrix.sync.aligned.m8n8.x4.shared.b16 {%0,%1,%2,%3}, [%4];"
                 : "=r"(r[0]), "=r"(r[1]), "=r"(r[2]), "=r"(r[3]) : "r"(a));
}
__device__ __forceinline__ void ldm4t(uint32_t (&r)[4], uint32_t a) {
    asm volatile("ldmatrix.sync.aligned.m8n8.x4.trans.shared.b16 {%0,%1,%2,%3}, [%4];"
                 : "=r"(r[0]), "=r"(r[1]), "=r"(r[2]), "=r"(r[3]) : "r"(a));
}
__device__ __forceinline__ void mma16(float (&d)[4], const uint32_t (&a)[4],
                                      const uint32_t (&b)[2]) {
    asm volatile(
        "mma.sync.aligned.m16n8k16.row.col.f32.f16.f16.f32 "
        "{%0,%1,%2,%3}, {%4,%5,%6,%7}, {%8,%9}, {%0,%1,%2,%3};"
        : "+f"(d[0]), "+f"(d[1]), "+f"(d[2]), "+f"(d[3])
        : "r"(a[0]), "r"(a[1]), "r"(a[2]), "r"(a[3]), "r"(b[0]), "r"(b[1]));
}

// exp(x) for |x| <= ~1.05 via Taylor to x^7 (rel err ~1.4e-5) — pure FMA.
__device__ __forceinline__ float exp_poly(float x)
{
    float r = fmaf(x, 1.f / 7.f, 1.f);
    r = fmaf(r * x, 1.f / 6.f, 1.f);
    r = fmaf(r * x, 1.f / 5.f, 1.f);
    r = fmaf(r * x, 1.f / 4.f, 1.f);
    r = fmaf(r * x, 1.f / 3.f, 1.f);
    r = fmaf(r * x, 0.5f, 1.f);
    return fmaf(r, x, 1.f);
}

// ===========================================================================
// FP16 warp-MMA GEMM: CTA BM_x128, 4 warps (2m x 2n), warp tile (BM_/2)x64,
// BK=64, 2-stage cp.async, ldmatrix frag loads, 3 CTAs/SM.
// BM_ = 128 for proj/score; 64 for mix (finer tiles -> smaller final-wave
// tail, which is raw wallclock on the last kernel).
// MODE 0: proj  — out half: acc + bias[m]; fused column sum-of-squares -> aux0
// MODE 1: score — y = acc * irq[m] * irk[n] (factorized rsqrt);
//                 out half exp(y); fused column sums of exp -> aux0
// MODE 2: mix   — out float: acc * (1 / aux0[n])
// ===========================================================================
#define BK 64
#define ARM_STR 72     // A row-major smem stride (halves): 64 + 8 pad
#define KM_STR 136     // k-major / B smem stride (halves): 128 + 8 pad

template <int MODE, int KDIM, bool AKM, int BM_, typename OutT>
__global__ __launch_bounds__(128, 3)
void gemm_h(const __half* __restrict__ A, int lda, size_t strA,
            const __half* __restrict__ B, int ldb, size_t strB,
            OutT* __restrict__ C, int ldc, size_t strC,
            const float* __restrict__ bias,
            float* __restrict__ aux0,
            const float* __restrict__ dq2_all,
            const float* __restrict__ dk2_all)
{
    constexpr int SA = AKM ? BK * KM_STR : BM_ * ARM_STR;   // halves per stage
    constexpr int SB = BK * KM_STR;
    constexpr int WMR = BM_ / 2;        // rows per warp slab
    constexpr int MI = WMR / 16;        // m16 tiles per warp
    extern __shared__ __half dsm[];
    __shared__ float s_aux[128];    // MODE1: rsqrt(dk2) ; MODE2: 1/S
    __shared__ float s_red[128];    // column partial reduce

    const int nb = blockIdx.z;
    const __half* An = A + (size_t)nb * strA;
    const __half* Bn = B + (size_t)nb * strB;
    OutT* Cn = C + (size_t)nb * strC;
    const int row0 = blockIdx.y * BM_;
    const int col0 = blockIdx.x * 128;

    const int tid = threadIdx.x;
    const int lane = tid & 31;
    const int wid = tid >> 5;
    const int wm = wid >> 1;
    const int wn = wid & 1;
    const int l7 = lane & 7;
    const int g = lane >> 3;

    s_red[tid] = 0.f;
    if (MODE == 1)
        s_aux[tid] = rsqrtf(fmaxf(dk2_all[(size_t)nb * BB + col0 + tid], 1e-6f));
    if (MODE == 2)
        s_aux[tid] = 1.f / aux0[(size_t)nb * BB + col0 + tid];

    float acc[MI][8][4] = {};

    auto ldA = [&](int st, int kt) {
        uint32_t sb = (uint32_t)__cvta_generic_to_shared(dsm + st * SA);
        if (!AKM) {
            #pragma unroll
            for (int i = tid; i < BM_ * 8; i += 128) {   // BM_ rows x 8 chunks
                int m = i >> 3, c = i & 7;
                cp16s(sb + (m * ARM_STR + c * 8) * 2,
                      An + (size_t)(row0 + m) * lda + kt * BK + c * 8);
            }
        } else {
            #pragma unroll
            for (int i = tid; i < 1024; i += 128) {      // 64 k-rows x 16 chunks
                int k = i >> 4, c = i & 15;
                cp16s(sb + (k * KM_STR + c * 8) * 2,
                      An + (size_t)(kt * BK + k) * lda + row0 + c * 8);
            }
        }
    };
    auto ldB = [&](int st, int kt) {
        uint32_t sb = (uint32_t)__cvta_generic_to_shared(dsm + 2 * SA + st * SB);
        #pragma unroll
        for (int i = tid; i < 1024; i += 128) {          // 64 k-rows x 16 chunks
            int k = i >> 4, c = i & 15;
            cp16s(sb + (k * KM_STR + c * 8) * 2,
                  Bn + (size_t)(kt * BK + k) * ldb + col0 + c * 8);
        }
    };

    constexpr int KT = KDIM / BK;

    ldA(0, 0); ldB(0, 0); CP_COMMIT();

    for (int kt = 0; kt < KT; kt++) {
        const int buf = kt & 1;
        if (kt + 1 < KT) {
            ldA(buf ^ 1, kt + 1);
            ldB(buf ^ 1, kt + 1);
            CP_COMMIT();
            asm volatile("cp.async.wait_group 1;");
        } else {
            asm volatile("cp.async.wait_group 0;");
        }
        __syncthreads();

        uint32_t aA = (uint32_t)__cvta_generic_to_shared(dsm + buf * SA);
        uint32_t aB = (uint32_t)__cvta_generic_to_shared(dsm + 2 * SA + buf * SB);

        #pragma unroll
        for (int ks = 0; ks < 4; ks++) {
            const int kb = ks * 16;
            uint32_t af[MI][4];
            uint32_t bf[8][2];

            #pragma unroll
            for (int mi = 0; mi < MI; mi++) {
                if (!AKM) {
                    int m = wm * WMR + mi * 16 + l7 + (g & 1) * 8;
                    int k = kb + (g >> 1) * 8;
                    ldm4(af[mi], aA + (m * ARM_STR + k) * 2);
                } else {
                    int k = kb + (g >> 1) * 8 + l7;
                    int m = wm * WMR + mi * 16 + (g & 1) * 8;
                    ldm4t(af[mi], aA + (k * KM_STR + m) * 2);
                }
            }
            #pragma unroll
            for (int j = 0; j < 4; j++) {
                int k = kb + (g & 1) * 8 + l7;
                int nn = wn * 64 + j * 16 + (g >> 1) * 8;
                uint32_t r[4];
                ldm4t(r, aB + (k * KM_STR + nn) * 2);
                bf[2 * j][0] = r[0];      bf[2 * j][1] = r[1];
                bf[2 * j + 1][0] = r[2];  bf[2 * j + 1][1] = r[3];
            }
            #pragma unroll
            for (int mi = 0; mi < MI; mi++)
                #pragma unroll
                for (int ni = 0; ni < 8; ni++)
                    mma16(acc[mi][ni], af[mi], bf[ni]);
        }
        __syncthreads();
    }

    // ---- epilogue (ni outer, mi inner; per-column partials for fusion) ----
    const int lr = lane >> 2, lc = lane & 3;

    float rA[MI], rB[MI];   // per-mi rows: bias (MODE0) or rsqrt(dq2) (MODE1)
    #pragma unroll
    for (int mi = 0; mi < MI; mi++) {
        const int m = row0 + wm * WMR + mi * 16 + lr;
        if (MODE == 0) { rA[mi] = bias[m]; rB[mi] = bias[m + 8]; }
        if (MODE == 1) {
            rA[mi] = rsqrtf(fmaxf(dq2_all[(size_t)nb * BB + m], 1e-6f));
            rB[mi] = rsqrtf(fmaxf(dq2_all[(size_t)nb * BB + m + 8], 1e-6f));
        }
    }

    #pragma unroll
    for (int ni = 0; ni < 8; ni++) {
        const int cl = wn * 64 + ni * 8 + 2 * lc;
        const int nn = col0 + cl;
        float c0 = 0.f, c1 = 0.f;
        float x0 = 0.f, x1 = 0.f;   // MODE1: irk ; MODE2: 1/S
        if (MODE == 1 || MODE == 2) { x0 = s_aux[cl]; x1 = s_aux[cl + 1]; }

        #pragma unroll
        for (int mi = 0; mi < MI; mi++) {
            const int m = row0 + wm * WMR + mi * 16 + lr;
            float v0 = acc[mi][ni][0], v1 = acc[mi][ni][1];
            float v2 = acc[mi][ni][2], v3 = acc[mi][ni][3];
            if (MODE == 0) {
                v0 += rA[mi]; v1 += rA[mi]; v2 += rB[mi]; v3 += rB[mi];
                c0 += v0 * v0 + v2 * v2;
                c1 += v1 * v1 + v3 * v3;
            } else if (MODE == 1) {
                v0 = exp_poly(v0 * rA[mi] * x0);
                v1 = exp_poly(v1 * rA[mi] * x1);
                v2 = exp_poly(v2 * rB[mi] * x0);
                v3 = exp_poly(v3 * rB[mi] * x1);
                c0 += v0 + v2;
                c1 += v1 + v3;
            } else {
                v0 *= x0; v1 *= x1; v2 *= x0; v3 *= x1;
            }
            if (MODE == 2) {
                *reinterpret_cast<float2*>((float*)&Cn[(size_t)m * ldc + nn]) =
                    make_float2(v0, v1);
                *reinterpret_cast<float2*>((float*)&Cn[(size_t)(m + 8) * ldc + nn]) =
                    make_float2(v2, v3);
            } else {
                *reinterpret_cast<__half2*>((__half*)&Cn[(size_t)m * ldc + nn]) =
                    __floats2half2_rn(v0, v1);
                *reinterpret_cast<__half2*>((__half*)&Cn[(size_t)(m + 8) * ldc + nn]) =
                    __floats2half2_rn(v2, v3);
            }
        }
        if (MODE == 0 || MODE == 1) {
            atomicAdd(&s_red[cl], c0);
            atomicAdd(&s_red[cl + 1], c1);
        }
    }

    if (MODE == 0 || MODE == 1) {
        __syncthreads();
        atomicAdd(&aux0[(size_t)nb * BB + col0 + tid], s_red[tid]);
    }
}

// ---------------------------------------------------------------------------
__global__ __launch_bounds__(256)
void to_half_kernel(const float* __restrict__ in, __half* __restrict__ out, int n4)
{
    int i = blockIdx.x * 256 + threadIdx.x;
    int stride = gridDim.x * 256;
    for (; i < n4; i += stride) {
        float4 v = reinterpret_cast<const float4*>(in)[i];
        __half2* o = reinterpret_cast<__half2*>(out) + 2 * i;
        o[0] = __floats2half2_rn(v.x, v.y);
        o[1] = __floats2half2_rn(v.z, v.w);
    }
}

// ---------------------------------------------------------------------------
extern "C" void kernel_launch(void* const* d_in, const int* in_sizes, int n_in,
                              void* d_out, int out_size)
{
    const float* X    = (const float*)d_in[0];
    const float* Wk_w = (const float*)d_in[1];
    const float* Wk_b = (const float*)d_in[2];
    const float* Wq_w = (const float*)d_in[3];
    const float* Wq_b = (const float*)d_in[4];
    float* Z = (float*)d_out;

    __half* Kh;  cudaGetSymbolAddress((void**)&Kh,  g_Kh);
    __half* Qh;  cudaGetSymbolAddress((void**)&Qh,  g_Qh);
    __half* Ed;  cudaGetSymbolAddress((void**)&Ed,  g_E);
    __half* Xh;  cudaGetSymbolAddress((void**)&Xh,  g_Xh);
    __half* Wkh; cudaGetSymbolAddress((void**)&Wkh, g_Wkh);
    __half* Wqh; cudaGetSymbolAddress((void**)&Wqh, g_Wqh);
    float* stats; cudaGetSymbolAddress((void**)&stats, g_stats);
    float* DK2 = stats;
    float* DQ2 = stats + NN * BB;
    float* Sv  = stats + 2 * NN * BB;

    const size_t sXn = (size_t)CC * BB;
    const size_t sYn = (size_t)BB * BB;

    // dynamic smem (2 stages, BK=64)
    constexpr int smem_rm   = 2 * (128 * ARM_STR + BK * KM_STR) * 2;  // 71,680 B
    constexpr int smem_akm  = 2 * (BK * KM_STR * 2) * 2;              // 69,632 B
    constexpr int smem_rm64 = 2 * (64 * ARM_STR + BK * KM_STR) * 2;   // 53,248 B

    static cudaStream_t s1 = nullptr, s2 = nullptr;
    static cudaEvent_t eS, e0, ek, eq;
    if (s1 == nullptr) {
        cudaStreamCreateWithFlags(&s1, cudaStreamNonBlocking);
        cudaStreamCreateWithFlags(&s2, cudaStreamNonBlocking);
        cudaEventCreateWithFlags(&eS, cudaEventDisableTiming);
        cudaEventCreateWithFlags(&e0, cudaEventDisableTiming);
        cudaEventCreateWithFlags(&ek, cudaEventDisableTiming);
        cudaEventCreateWithFlags(&eq, cudaEventDisableTiming);
        cudaFuncSetAttribute(gemm_h<0, CC, false, 128, __half>,
                             cudaFuncAttributeMaxDynamicSharedMemorySize, smem_rm);
        cudaFuncSetAttribute(gemm_h<1, CC, true, 128, __half>,
                             cudaFuncAttributeMaxDynamicSharedMemorySize, smem_akm);
        cudaFuncSetAttribute(gemm_h<2, BB, false, 64, float>,
                             cudaFuncAttributeMaxDynamicSharedMemorySize, smem_rm64);
    }

    // ---- fork point (default stream = capture stream) ----
    cudaEventRecord(eS, 0);

    // default: zero fused accumulators + convert X
    cudaMemsetAsync(stats, 0, 3 * NN * BB * sizeof(float));
    to_half_kernel<<<2048, 256>>>(X, Xh, (int)(NN * sXn / 4));
    cudaEventRecord(e0, 0);

    // s1: convert Wk, then proj K (dep: X converted)
    cudaStreamWaitEvent(s1, eS, 0);
    to_half_kernel<<<256, 256, 0, s1>>>(Wk_w, Wkh, CC * CC / 4);
    cudaStreamWaitEvent(s1, e0, 0);
    gemm_h<0, CC, false, 128, __half><<<dim3(BB / 128, CC / 128, NN), 128, smem_rm, s1>>>(
        Wkh, CC, 0, Xh, BB, sXn, Kh, BB, sXn, Wk_b, DK2, nullptr, nullptr);
    cudaEventRecord(ek, s1);

    // s2: convert Wq, then proj Q
    cudaStreamWaitEvent(s2, eS, 0);
    to_half_kernel<<<256, 256, 0, s2>>>(Wq_w, Wqh, CC * CC / 4);
    cudaStreamWaitEvent(s2, e0, 0);
    gemm_h<0, CC, false, 128, __half><<<dim3(BB / 128, CC / 128, NN), 128, smem_rm, s2>>>(
        Wqh, CC, 0, Xh, BB, sXn, Qh, BB, sXn, Wq_b, DQ2, nullptr, nullptr);
    cudaEventRecord(eq, s2);

    // ---- join: default stream waits for both projections ----
    cudaStreamWaitEvent(0, ek, 0);
    cudaStreamWaitEvent(0, eq, 0);

    // 2) scores -> E = exp(cosine), + fused column-sum S (softmax denominator)
    gemm_h<1, CC, true, 128, __half><<<dim3(BB / 128, BB / 128, NN), 128, smem_akm>>>(
        Qh, BB, sXn, Kh, BB, sXn, Ed, BB, sYn, nullptr, Sv, DQ2, DK2);

    // 3) mix: Z = (X @ E) * diag(1/S) — M=64 tiles for tighter final-wave packing
    gemm_h<2, BB, false, 64, float><<<dim3(BB / 128, CC / 64, NN), 128, smem_rm64>>>(
        Xh, BB, sXn, Ed, BB, sYn, Z, BB, sXn, nullptr, Sv, nullptr, nullptr);
}

// round 17
// speedup vs baseline: 1.1095x; 1.0614x over previous
#include <cuda_runtime.h>
#include <cuda_fp16.h>
#include <math.h>
#include <stdint.h>

#define NN 8
#define CC 1024
#define BB 2048

// ---- scratch (device globals; no allocation allowed) ----
__device__ __half g_Kh[(size_t)NN * CC * BB];   // K [o][b] fp16
__device__ __half g_Qh[(size_t)NN * CC * BB];   // Q [o][b] fp16
__device__ __half g_E [(size_t)NN * BB * BB];   // E = exp(Y) [b][k'] fp16
__device__ __half g_Xh[(size_t)NN * CC * BB];   // X fp16 [c][b]
__device__ __half g_Wkh[CC * CC];
__device__ __half g_Wqh[CC * CC];
__device__ float  g_stats[3 * NN * BB];         // [DK2 | DQ2 | S], zeroed each launch

// ---------------------------------------------------------------------------
__device__ __forceinline__ void cp16s(uint32_t s, const __half* g) {
    asm volatile("cp.async.cg.shared.global [%0], [%1], 16;" :: "r"(s), "l"(g));
}
#define CP_COMMIT() asm volatile("cp.async.commit_group;")

__device__ __forceinline__ void ldm4(uint32_t (&r)[4], uint32_t a) {
    asm volatile("ldmatrix.sync.aligned.m8n8.x4.shared.b16 {%0,%1,%2,%3}, [%4];"
                 : "=r"(r[0]), "=r"(r[1]), "=r"(r[2]), "=r"(r[3]) : "r"(a));
}
__device__ __forceinline__ void ldm4t(uint32_t (&r)[4], uint32_t a) {
    asm volatile("ldmatrix.sync.aligned.m8n8.x4.trans.shared.b16 {%0,%1,%2,%3}, [%4];"
                 : "=r"(r[0]), "=r"(r[1]), "=r"(r[2]), "=r"(r[3]) : "r"(a));
}
__device__ __forceinline__ void mma16(float (&d)[4], const uint32_t (&a)[4],
                                      const uint32_t (&b)[2]) {
    asm volatile(
        "mma.sync.aligned.m16n8k16.row.col.f32.f16.f16.f32 "
        "{%0,%1,%2,%3}, {%4,%5,%6,%7}, {%8,%9}, {%0,%1,%2,%3};"
        : "+f"(d[0]), "+f"(d[1]), "+f"(d[2]), "+f"(d[3])
        : "r"(a[0]), "r"(a[1]), "r"(a[2]), "r"(a[3]), "r"(b[0]), "r"(b[1]));
}

// exp(x) for |x| <= ~1.05 via Taylor to x^7 (rel err ~1.4e-5) — pure FMA.
__device__ __forceinline__ float exp_poly(float x)
{
    float r = fmaf(x, 1.f / 7.f, 1.f);
    r = fmaf(r * x, 1.f / 6.f, 1.f);
    r = fmaf(r * x, 1.f / 5.f, 1.f);
    r = fmaf(r * x, 1.f / 4.f, 1.f);
    r = fmaf(r * x, 1.f / 3.f, 1.f);
    r = fmaf(r * x, 0.5f, 1.f);
    return fmaf(r, x, 1.f);
}

// ===========================================================================
// FP16 warp-MMA GEMM: CTA 128x128, 4 warps (2m x 2n), warp tile 64x64,
// BK=64, 2-stage cp.async, ldmatrix frag loads, 3 CTAs/SM.
// MODE 0: proj  — out half: acc + bias[m]; fused column sum-of-squares -> aux0
// MODE 1: score — y = acc * irq[m] * irk[n] (factorized rsqrt);
//                 out half exp(y); fused column sums of exp -> aux0
// MODE 2: mix   — out float: acc * (1 / aux0[n])
// Column partials are butterfly-reduced over the 8 lanes sharing a column
// pair before touching smem atomics (64 -> 8 atomics/warp/ni, conflict-free).
// ===========================================================================
#define BK 64
#define ARM_STR 72     // A row-major smem stride (halves): 64 + 8 pad
#define KM_STR 136     // k-major / B smem stride (halves): 128 + 8 pad

template <int MODE, int KDIM, bool AKM, typename OutT>
__global__ __launch_bounds__(128, 3)
void gemm_h(const __half* __restrict__ A, int lda, size_t strA,
            const __half* __restrict__ B, int ldb, size_t strB,
            OutT* __restrict__ C, int ldc, size_t strC,
            const float* __restrict__ bias,
            float* __restrict__ aux0,
            const float* __restrict__ dq2_all,
            const float* __restrict__ dk2_all)
{
    constexpr int SA = AKM ? BK * KM_STR : 128 * ARM_STR;   // halves per stage
    constexpr int SB = BK * KM_STR;
    extern __shared__ __half dsm[];
    __shared__ float s_aux[128];    // MODE1: rsqrt(dk2) ; MODE2: 1/S
    __shared__ float s_red[128];    // column partial reduce

    const int nb = blockIdx.z;
    const __half* An = A + (size_t)nb * strA;
    const __half* Bn = B + (size_t)nb * strB;
    OutT* Cn = C + (size_t)nb * strC;
    const int row0 = blockIdx.y * 128;
    const int col0 = blockIdx.x * 128;

    const int tid = threadIdx.x;
    const int lane = tid & 31;
    const int wid = tid >> 5;
    const int wm = wid >> 1;
    const int wn = wid & 1;
    const int l7 = lane & 7;
    const int g = lane >> 3;

    s_red[tid] = 0.f;
    if (MODE == 1)
        s_aux[tid] = rsqrtf(fmaxf(dk2_all[(size_t)nb * BB + col0 + tid], 1e-6f));
    if (MODE == 2)
        s_aux[tid] = 1.f / aux0[(size_t)nb * BB + col0 + tid];

    float acc[4][8][4] = {};

    auto ldA = [&](int st, int kt) {
        uint32_t sb = (uint32_t)__cvta_generic_to_shared(dsm + st * SA);
        if (!AKM) {
            #pragma unroll
            for (int i = tid; i < 1024; i += 128) {      // 128 rows x 8 chunks
                int m = i >> 3, c = i & 7;
                cp16s(sb + (m * ARM_STR + c * 8) * 2,
                      An + (size_t)(row0 + m) * lda + kt * BK + c * 8);
            }
        } else {
            #pragma unroll
            for (int i = tid; i < 1024; i += 128) {      // 64 k-rows x 16 chunks
                int k = i >> 4, c = i & 15;
                cp16s(sb + (k * KM_STR + c * 8) * 2,
                      An + (size_t)(kt * BK + k) * lda + row0 + c * 8);
            }
        }
    };
    auto ldB = [&](int st, int kt) {
        uint32_t sb = (uint32_t)__cvta_generic_to_shared(dsm + 2 * SA + st * SB);
        #pragma unroll
        for (int i = tid; i < 1024; i += 128) {          // 64 k-rows x 16 chunks
            int k = i >> 4, c = i & 15;
            cp16s(sb + (k * KM_STR + c * 8) * 2,
                  Bn + (size_t)(kt * BK + k) * ldb + col0 + c * 8);
        }
    };

    constexpr int KT = KDIM / BK;

    ldA(0, 0); ldB(0, 0); CP_COMMIT();

    for (int kt = 0; kt < KT; kt++) {
        const int buf = kt & 1;
        if (kt + 1 < KT) {
            ldA(buf ^ 1, kt + 1);
            ldB(buf ^ 1, kt + 1);
            CP_COMMIT();
            asm volatile("cp.async.wait_group 1;");
        } else {
            asm volatile("cp.async.wait_group 0;");
        }
        __syncthreads();

        uint32_t aA = (uint32_t)__cvta_generic_to_shared(dsm + buf * SA);
        uint32_t aB = (uint32_t)__cvta_generic_to_shared(dsm + 2 * SA + buf * SB);

        #pragma unroll
        for (int ks = 0; ks < 4; ks++) {
            const int kb = ks * 16;
            uint32_t af[4][4];
            uint32_t bf[8][2];

            #pragma unroll
            for (int mi = 0; mi < 4; mi++) {
                if (!AKM) {
                    int m = wm * 64 + mi * 16 + l7 + (g & 1) * 8;
                    int k = kb + (g >> 1) * 8;
                    ldm4(af[mi], aA + (m * ARM_STR + k) * 2);
                } else {
                    int k = kb + (g >> 1) * 8 + l7;
                    int m = wm * 64 + mi * 16 + (g & 1) * 8;
                    ldm4t(af[mi], aA + (k * KM_STR + m) * 2);
                }
            }
            #pragma unroll
            for (int j = 0; j < 4; j++) {
                int k = kb + (g & 1) * 8 + l7;
                int nn = wn * 64 + j * 16 + (g >> 1) * 8;
                uint32_t r[4];
                ldm4t(r, aB + (k * KM_STR + nn) * 2);
                bf[2 * j][0] = r[0];      bf[2 * j][1] = r[1];
                bf[2 * j + 1][0] = r[2];  bf[2 * j + 1][1] = r[3];
            }
            #pragma unroll
            for (int mi = 0; mi < 4; mi++)
                #pragma unroll
                for (int ni = 0; ni < 8; ni++)
                    mma16(acc[mi][ni], af[mi], bf[ni]);
        }
        __syncthreads();
    }

    // ---- epilogue (ni outer, mi inner; per-column partials for fusion) ----
    const int lr = lane >> 2, lc = lane & 3;

    float rA[4], rB[4];   // per-mi rows: bias (MODE0) or rsqrt(dq2) (MODE1)
    #pragma unroll
    for (int mi = 0; mi < 4; mi++) {
        const int m = row0 + wm * 64 + mi * 16 + lr;
        if (MODE == 0) { rA[mi] = bias[m]; rB[mi] = bias[m + 8]; }
        if (MODE == 1) {
            rA[mi] = rsqrtf(fmaxf(dq2_all[(size_t)nb * BB + m], 1e-6f));
            rB[mi] = rsqrtf(fmaxf(dq2_all[(size_t)nb * BB + m + 8], 1e-6f));
        }
    }

    #pragma unroll
    for (int ni = 0; ni < 8; ni++) {
        const int cl = wn * 64 + ni * 8 + 2 * lc;
        const int nn = col0 + cl;
        float c0 = 0.f, c1 = 0.f;
        float x0 = 0.f, x1 = 0.f;   // MODE1: irk ; MODE2: 1/S
        if (MODE == 1 || MODE == 2) { x0 = s_aux[cl]; x1 = s_aux[cl + 1]; }

        #pragma unroll
        for (int mi = 0; mi < 4; mi++) {
            const int m = row0 + wm * 64 + mi * 16 + lr;
            float v0 = acc[mi][ni][0], v1 = acc[mi][ni][1];
            float v2 = acc[mi][ni][2], v3 = acc[mi][ni][3];
            if (MODE == 0) {
                v0 += rA[mi]; v1 += rA[mi]; v2 += rB[mi]; v3 += rB[mi];
                c0 += v0 * v0 + v2 * v2;
                c1 += v1 * v1 + v3 * v3;
            } else if (MODE == 1) {
                v0 = exp_poly(v0 * rA[mi] * x0);
                v1 = exp_poly(v1 * rA[mi] * x1);
                v2 = exp_poly(v2 * rB[mi] * x0);
                v3 = exp_poly(v3 * rB[mi] * x1);
                c0 += v0 + v2;
                c1 += v1 + v3;
            } else {
                v0 *= x0; v1 *= x1; v2 *= x0; v3 *= x1;
            }
            if (MODE == 2) {
                *reinterpret_cast<float2*>((float*)&Cn[(size_t)m * ldc + nn]) =
                    make_float2(v0, v1);
                *reinterpret_cast<float2*>((float*)&Cn[(size_t)(m + 8) * ldc + nn]) =
                    make_float2(v2, v3);
            } else {
                *reinterpret_cast<__half2*>((__half*)&Cn[(size_t)m * ldc + nn]) =
                    __floats2half2_rn(v0, v1);
                *reinterpret_cast<__half2*>((__half*)&Cn[(size_t)(m + 8) * ldc + nn]) =
                    __floats2half2_rn(v2, v3);
            }
        }
        if (MODE == 0 || MODE == 1) {
            // butterfly-reduce over the 8 lanes (lr bits = lane bits 2..4)
            // that share this column pair, then one atomic from lanes 0..3.
            #pragma unroll
            for (int o = 4; o <= 16; o <<= 1) {
                c0 += __shfl_xor_sync(0xFFFFFFFFu, c0, o);
                c1 += __shfl_xor_sync(0xFFFFFFFFu, c1, o);
            }
            if (lane < 4) {
                atomicAdd(&s_red[cl], c0);
                atomicAdd(&s_red[cl + 1], c1);
            }
        }
    }

    if (MODE == 0 || MODE == 1) {
        __syncthreads();
        atomicAdd(&aux0[(size_t)nb * BB + col0 + tid], s_red[tid]);
    }
}

// ---------------------------------------------------------------------------
__global__ __launch_bounds__(256)
void to_half_kernel(const float* __restrict__ in, __half* __restrict__ out, int n4)
{
    int i = blockIdx.x * 256 + threadIdx.x;
    int stride = gridDim.x * 256;
    for (; i < n4; i += stride) {
        float4 v = reinterpret_cast<const float4*>(in)[i];
        __half2* o = reinterpret_cast<__half2*>(out) + 2 * i;
        o[0] = __floats2half2_rn(v.x, v.y);
        o[1] = __floats2half2_rn(v.z, v.w);
    }
}

// ---------------------------------------------------------------------------
extern "C" void kernel_launch(void* const* d_in, const int* in_sizes, int n_in,
                              void* d_out, int out_size)
{
    const float* X    = (const float*)d_in[0];
    const float* Wk_w = (const float*)d_in[1];
    const float* Wk_b = (const float*)d_in[2];
    const float* Wq_w = (const float*)d_in[3];
    const float* Wq_b = (const float*)d_in[4];
    float* Z = (float*)d_out;

    __half* Kh;  cudaGetSymbolAddress((void**)&Kh,  g_Kh);
    __half* Qh;  cudaGetSymbolAddress((void**)&Qh,  g_Qh);
    __half* Ed;  cudaGetSymbolAddress((void**)&Ed,  g_E);
    __half* Xh;  cudaGetSymbolAddress((void**)&Xh,  g_Xh);
    __half* Wkh; cudaGetSymbolAddress((void**)&Wkh, g_Wkh);
    __half* Wqh; cudaGetSymbolAddress((void**)&Wqh, g_Wqh);
    float* stats; cudaGetSymbolAddress((void**)&stats, g_stats);
    float* DK2 = stats;
    float* DQ2 = stats + NN * BB;
    float* Sv  = stats + 2 * NN * BB;

    const size_t sXn = (size_t)CC * BB;
    const size_t sYn = (size_t)BB * BB;

    // dynamic smem (2 stages, BK=64)
    constexpr int smem_rm  = 2 * (128 * ARM_STR + BK * KM_STR) * 2;  // 71,680 B
    constexpr int smem_akm = 2 * (BK * KM_STR * 2) * 2;              // 69,632 B

    static cudaStream_t s1 = nullptr, s2 = nullptr;
    static cudaEvent_t eS, e0, ek, eq;
    if (s1 == nullptr) {
        cudaStreamCreateWithFlags(&s1, cudaStreamNonBlocking);
        cudaStreamCreateWithFlags(&s2, cudaStreamNonBlocking);
        cudaEventCreateWithFlags(&eS, cudaEventDisableTiming);
        cudaEventCreateWithFlags(&e0, cudaEventDisableTiming);
        cudaEventCreateWithFlags(&ek, cudaEventDisableTiming);
        cudaEventCreateWithFlags(&eq, cudaEventDisableTiming);
        cudaFuncSetAttribute(gemm_h<0, CC, false, __half>,
                             cudaFuncAttributeMaxDynamicSharedMemorySize, smem_rm);
        cudaFuncSetAttribute(gemm_h<1, CC, true, __half>,
                             cudaFuncAttributeMaxDynamicSharedMemorySize, smem_akm);
        cudaFuncSetAttribute(gemm_h<2, BB, false, float>,
                             cudaFuncAttributeMaxDynamicSharedMemorySize, smem_rm);
    }

    // ---- fork point (default stream = capture stream) ----
    cudaEventRecord(eS, 0);

    // default: zero fused accumulators + convert X
    cudaMemsetAsync(stats, 0, 3 * NN * BB * sizeof(float));
    to_half_kernel<<<2048, 256>>>(X, Xh, (int)(NN * sXn / 4));
    cudaEventRecord(e0, 0);

    // s1: convert Wk, then proj K (dep: X converted)
    cudaStreamWaitEvent(s1, eS, 0);
    to_half_kernel<<<256, 256, 0, s1>>>(Wk_w, Wkh, CC * CC / 4);
    cudaStreamWaitEvent(s1, e0, 0);
    gemm_h<0, CC, false, __half><<<dim3(BB / 128, CC / 128, NN), 128, smem_rm, s1>>>(
        Wkh, CC, 0, Xh, BB, sXn, Kh, BB, sXn, Wk_b, DK2, nullptr, nullptr);
    cudaEventRecord(ek, s1);

    // s2: convert Wq, then proj Q
    cudaStreamWaitEvent(s2, eS, 0);
    to_half_kernel<<<256, 256, 0, s2>>>(Wq_w, Wqh, CC * CC / 4);
    cudaStreamWaitEvent(s2, e0, 0);
    gemm_h<0, CC, false, __half><<<dim3(BB / 128, CC / 128, NN), 128, smem_rm, s2>>>(
        Wqh, CC, 0, Xh, BB, sXn, Qh, BB, sXn, Wq_b, DQ2, nullptr, nullptr);
    cudaEventRecord(eq, s2);

    // ---- join: default stream waits for both projections ----
    cudaStreamWaitEvent(0, ek, 0);
    cudaStreamWaitEvent(0, eq, 0);

    // 2) scores -> E = exp(cosine), + fused column-sum S (softmax denominator)
    gemm_h<1, CC, true, __half><<<dim3(BB / 128, BB / 128, NN), 128, smem_akm>>>(
        Qh, BB, sXn, Kh, BB, sXn, Ed, BB, sYn, nullptr, Sv, DQ2, DK2);

    // 3) mix: Z = (X @ E) * diag(1/S)   (fused softmax division)
    gemm_h<2, BB, false, float><<<dim3(BB / 128, CC / 128, NN), 128, smem_rm>>>(
        Xh, BB, sXn, Ed, BB, sYn, Z, BB, sXn, nullptr, Sv, nullptr, nullptr);
}